// round 14
// baseline (speedup 1.0000x reference)
#include <cuda_runtime.h>
#include <math.h>
#include <math_constants.h>

// Router: logits = x[8192,4096] @ W[4096,64]; per-token top-8 (desc, ties->lower idx);
// softmax over the 8 selected logits.
//
// FROZEN ARITHMETIC (bit-identical to passing R10..R13 kernels):
//   per logit: 13 k-panels (12x320 + 256), ascending; within a panel one plain
//   fp32 FMA chain over ascending k; panel sums folded sequentially with add.rn;
//   topk desc tie->lower-index; softmax = expf(v - top0), fadd_rn chain, fdiv_rn.
//
// R14: single fused kernel. CTA = 32 tokens x 64 experts over full k; panel
// chunks fold in registers; topk+softmax inline. No scratch, no second kernel.
//
// Output layout: d_out[0 .. T*8)     = normalized weights (float)
//                d_out[T*8 .. 2*T*8) = selected expert indices (as float)

#define T_TOK 8192
#define D_DIM 4096
#define E_EXP 64
#define TOPK  8
#define TBLK  32                  // tokens per CTA
#define KC    32                  // k-tile in shared
#define NT    (D_DIM / KC)        // 128 tiles
// panels: 12 x 320 (10 tiles) + 1 x 256 (8 tiles)

__device__ __forceinline__ void ffma2(unsigned long long& acc,
                                      unsigned long long a,
                                      unsigned long long b) {
    asm volatile("fma.rn.f32x2 %0, %1, %2, %0;" : "+l"(acc) : "l"(a), "l"(b));
}
__device__ __forceinline__ float fadd_rn(float a, float b) {
    float r; asm("add.rn.f32 %0, %1, %2;" : "=f"(r) : "f"(a), "f"(b)); return r;
}
__device__ __forceinline__ float fdiv_rn(float a, float b) {
    float r; asm("div.rn.f32 %0, %1, %2;" : "=f"(r) : "f"(a), "f"(b)); return r;
}
__device__ __forceinline__ void unpack2(unsigned long long v, float& lo, float& hi) {
    asm("mov.b64 {%0, %1}, %2;" : "=f"(lo), "=f"(hi) : "l"(v));
}

__global__ __launch_bounds__(256, 2) void router_fused_kernel(
    const float* __restrict__ x,     // [T, D]
    const float* __restrict__ w,     // [D, E]
    float* __restrict__ out)         // [2*T*8]
{
    __shared__ float xs[2][KC][38];    // [buf][k][token], pad 38 (8B-aligned rows)
    __shared__ float wsd[2][KC][132];  // [buf][k][2*expert] duplicated
    __shared__ float lgs[TBLK][65];    // final logits [token][expert]

    const int tid  = threadIdx.x;
    const int wid  = tid >> 5;
    const int lane = tid & 31;
    const int p    = lane & 15;       // token pair: tokens 2p, 2p+1
    const int d    = lane >> 4;       // expert quad selector
    const int ebase = 8 * wid + 4 * d;   // this thread's 4 experts
    const int tok0 = blockIdx.x * TBLK;

    // running totals + current panel chunk: 4 experts x 1 token-pair
    float ta[4] = {0.f, 0.f, 0.f, 0.f};   // token 2p
    float tb[4] = {0.f, 0.f, 0.f, 0.f};   // token 2p+1
    unsigned long long acc[4] = {0ull, 0ull, 0ull, 0ull};

    // load addressing
    const int xtok = tid >> 3;        // 0..31
    const int xkq  = tid & 7;         // float4 index within 32-k row
    const int wrow0 = tid >> 4;       // + 16*r
    const int wm    = tid & 15;

    float4 xv, wv0, wv1;

    // ---- preload tile 0 ----
    xv  = *reinterpret_cast<const float4*>(&x[(size_t)(tok0 + xtok) * D_DIM + 4 * xkq]);
    wv0 = *reinterpret_cast<const float4*>(&w[(size_t)(wrow0) * E_EXP + 4 * wm]);
    wv1 = *reinterpret_cast<const float4*>(&w[(size_t)(wrow0 + 16) * E_EXP + 4 * wm]);
    {
        xs[0][4 * xkq + 0][xtok] = xv.x;
        xs[0][4 * xkq + 1][xtok] = xv.y;
        xs[0][4 * xkq + 2][xtok] = xv.z;
        xs[0][4 * xkq + 3][xtok] = xv.w;
        wsd[0][wrow0][8 * wm + 0] = wv0.x; wsd[0][wrow0][8 * wm + 1] = wv0.x;
        wsd[0][wrow0][8 * wm + 2] = wv0.y; wsd[0][wrow0][8 * wm + 3] = wv0.y;
        wsd[0][wrow0][8 * wm + 4] = wv0.z; wsd[0][wrow0][8 * wm + 5] = wv0.z;
        wsd[0][wrow0][8 * wm + 6] = wv0.w; wsd[0][wrow0][8 * wm + 7] = wv0.w;
        wsd[0][wrow0 + 16][8 * wm + 0] = wv1.x; wsd[0][wrow0 + 16][8 * wm + 1] = wv1.x;
        wsd[0][wrow0 + 16][8 * wm + 2] = wv1.y; wsd[0][wrow0 + 16][8 * wm + 3] = wv1.y;
        wsd[0][wrow0 + 16][8 * wm + 4] = wv1.z; wsd[0][wrow0 + 16][8 * wm + 5] = wv1.z;
        wsd[0][wrow0 + 16][8 * wm + 6] = wv1.w; wsd[0][wrow0 + 16][8 * wm + 7] = wv1.w;
    }
    __syncthreads();

#pragma unroll 1
    for (int t = 0; t < NT; t++) {
        const int cur = t & 1;
        const bool more = (t + 1) < NT;

        // prefetch tile t+1
        if (more) {
            const int k0 = KC * (t + 1);
            xv  = *reinterpret_cast<const float4*>(
                &x[(size_t)(tok0 + xtok) * D_DIM + k0 + 4 * xkq]);
            wv0 = *reinterpret_cast<const float4*>(&w[(size_t)(k0 + wrow0) * E_EXP + 4 * wm]);
            wv1 = *reinterpret_cast<const float4*>(&w[(size_t)(k0 + wrow0 + 16) * E_EXP + 4 * wm]);
        }

        // compute 32 k on current buffer
#pragma unroll
        for (int kk = 0; kk < KC; kk++) {
            ulonglong2 q0 = *reinterpret_cast<const ulonglong2*>(&wsd[cur][kk][16 * wid + 8 * d]);
            ulonglong2 q1 = *reinterpret_cast<const ulonglong2*>(&wsd[cur][kk][16 * wid + 8 * d + 4]);
            unsigned long long xp = *reinterpret_cast<const unsigned long long*>(&xs[cur][kk][2 * p]);
            ffma2(acc[0], xp, q0.x);
            ffma2(acc[1], xp, q0.y);
            ffma2(acc[2], xp, q1.x);
            ffma2(acc[3], xp, q1.y);
        }

        // stage tile t+1
        if (more) {
            const int nxt = cur ^ 1;
            xs[nxt][4 * xkq + 0][xtok] = xv.x;
            xs[nxt][4 * xkq + 1][xtok] = xv.y;
            xs[nxt][4 * xkq + 2][xtok] = xv.z;
            xs[nxt][4 * xkq + 3][xtok] = xv.w;
            wsd[nxt][wrow0][8 * wm + 0] = wv0.x; wsd[nxt][wrow0][8 * wm + 1] = wv0.x;
            wsd[nxt][wrow0][8 * wm + 2] = wv0.y; wsd[nxt][wrow0][8 * wm + 3] = wv0.y;
            wsd[nxt][wrow0][8 * wm + 4] = wv0.z; wsd[nxt][wrow0][8 * wm + 5] = wv0.z;
            wsd[nxt][wrow0][8 * wm + 6] = wv0.w; wsd[nxt][wrow0][8 * wm + 7] = wv0.w;
            wsd[nxt][wrow0 + 16][8 * wm + 0] = wv1.x; wsd[nxt][wrow0 + 16][8 * wm + 1] = wv1.x;
            wsd[nxt][wrow0 + 16][8 * wm + 2] = wv1.y; wsd[nxt][wrow0 + 16][8 * wm + 3] = wv1.y;
            wsd[nxt][wrow0 + 16][8 * wm + 4] = wv1.z; wsd[nxt][wrow0 + 16][8 * wm + 5] = wv1.z;
            wsd[nxt][wrow0 + 16][8 * wm + 6] = wv1.w; wsd[nxt][wrow0 + 16][8 * wm + 7] = wv1.w;
        }

        // panel boundary: fold chunk into running totals (ascending panel order)
        const bool fold_now = (t < 120) ? ((t % 10) == 9) : (t == NT - 1);
        if (fold_now) {
#pragma unroll
            for (int e = 0; e < 4; e++) {
                float a, b;
                unpack2(acc[e], a, b);
                ta[e] = fadd_rn(ta[e], a);
                tb[e] = fadd_rn(tb[e], b);
                acc[e] = 0ull;
            }
        }
        __syncthreads();
    }

    // ---- write logits to shared ----
#pragma unroll
    for (int e = 0; e < 4; e++) {
        lgs[2 * p + 0][ebase + e] = ta[e];
        lgs[2 * p + 1][ebase + e] = tb[e];
    }
    __syncthreads();

    // ---- topk + softmax: warp wid handles tokens 4*wid .. 4*wid+3 ----
#pragma unroll 1
    for (int j = 0; j < 4; j++) {
        const int tl = 4 * wid + j;
        float va = lgs[tl][lane];
        float vb = lgs[tl][lane + 32];
        const int ea = lane, eb = lane + 32;

        float topv[TOPK];
        int   topi[TOPK];
#pragma unroll
        for (int s = 0; s < TOPK; s++) {
            float v; int e;
            if (va >= vb) { v = va; e = ea; } else { v = vb; e = eb; }
#pragma unroll
            for (int off = 16; off > 0; off >>= 1) {
                float v2 = __shfl_xor_sync(0xffffffffu, v, off);
                int   e2 = __shfl_xor_sync(0xffffffffu, e, off);
                if (v2 > v || (v2 == v && e2 < e)) { v = v2; e = e2; }
            }
            topv[s] = v;
            topi[s] = e;
            if (ea == e) va = -CUDART_INF_F;
            if (eb == e) vb = -CUDART_INF_F;
        }

        if (lane == 0) {
            const float m = topv[0];
            float ev[TOPK];
            float ssum = 0.f;
#pragma unroll
            for (int q = 0; q < TOPK; q++) { ev[q] = expf(topv[q] - m); ssum = fadd_rn(ssum, ev[q]); }
            const int gtok = tok0 + tl;
            const size_t base = (size_t)gtok * TOPK;
#pragma unroll
            for (int q = 0; q < TOPK; q++) {
                out[base + q] = fdiv_rn(ev[q], ssum);
                out[(size_t)T_TOK * TOPK + base + q] = (float)topi[q];
            }
        }
    }
}

extern "C" void kernel_launch(void* const* d_in, const int* in_sizes, int n_in,
                              void* d_out, int out_size) {
    const float* x = (const float*)d_in[0];   // [8192, 4096]
    const float* w = (const float*)d_in[1];   // [4096, 64]
    float* out = (float*)d_out;

    router_fused_kernel<<<T_TOK / TBLK, 256>>>(x, w, out);
}

// round 16
// speedup vs baseline: 1.6960x; 1.6960x over previous
#include <cuda_runtime.h>
#include <math.h>
#include <math_constants.h>

// Router: logits = x[8192,4096] @ W[4096,64]; per-token top-8 (desc, ties->lower idx);
// softmax over the 8 selected logits.
//
// FROZEN ARITHMETIC (bit-identical to passing R10..R14 kernels):
//   per logit: 13 k-panels (12x320 + 256), ascending; within a panel one plain
//   fp32 FMA chain over ascending k; panel sums folded sequentially with add.rn;
//   topk desc tie->lower-index (index-masked); softmax = expf(v - top0),
//   fadd_rn chain, fdiv_rn.
//
// R15 schedule: GEMM retiled to 2.0 LDS-bytes/FFMA2 (8 tok x 8 exp per thread),
// split-K over 13 panels; fold kernel with fully-coalesced LDG.128 reads.
//
// Output layout: d_out[0 .. T*8)     = normalized weights (float)
//                d_out[T*8 .. 2*T*8) = selected expert indices (as float)

#define T_TOK 8192
#define D_DIM 4096
#define E_EXP 64
#define TOPK  8
#define KBLK  320                 // Eigen-style k-panel
#define NPAN  13                  // 12*320 + 256 = 4096
#define TBLK  256                 // tokens per GEMM CTA
#define NTB   (T_TOK / TBLK)      // 32
#define KC    8                   // k-tile in shared

// panel partial sums: [panel][tokblock][expert][token-in-block]  (27.3 MB)
__device__ float g_part[NPAN][NTB][E_EXP][TBLK];

__device__ __forceinline__ void ffma2(unsigned long long& acc,
                                      unsigned long long a,
                                      unsigned long long b) {
    asm volatile("fma.rn.f32x2 %0, %1, %2, %0;" : "+l"(acc) : "l"(a), "l"(b));
}
__device__ __forceinline__ float fadd_rn(float a, float b) {
    float r; asm("add.rn.f32 %0, %1, %2;" : "=f"(r) : "f"(a), "f"(b)); return r;
}
__device__ __forceinline__ float fdiv_rn(float a, float b) {
    float r; asm("div.rn.f32 %0, %1, %2;" : "=f"(r) : "f"(a), "f"(b)); return r;
}
__device__ __forceinline__ void unpack2(unsigned long long v, float& lo, float& hi) {
    asm("mov.b64 {%0, %1}, %2;" : "=f"(lo), "=f"(hi) : "l"(v));
}

__global__ __launch_bounds__(256, 2) void gemm_panel_kernel(
    const float* __restrict__ x,     // [T, D]
    const float* __restrict__ w)     // [D, E]
{
    __shared__ float xs[2][KC][260];   // [buf][k][token], pad 260 (rows 16B-aligned)
    __shared__ float wsd[2][KC][132];  // [buf][k][2*expert] duplicated

    const int tid  = threadIdx.x;
    const int wid  = tid >> 5;       // warp -> experts 8*wid .. 8*wid+7
    const int lane = tid & 31;       // lane -> tokens 8*lane .. 8*lane+7
    const int tok0 = blockIdx.x * TBLK;
    const int p    = blockIdx.y;     // panel
    const int kbeg = p * KBLK;
    const int ntile = (p == NPAN - 1) ? (D_DIM - (NPAN - 1) * KBLK) / KC : KBLK / KC;

    unsigned long long acc[4][8];    // [token-pair j][expert e]
#pragma unroll
    for (int j = 0; j < 4; j++)
#pragma unroll
        for (int e = 0; e < 8; e++) acc[j][e] = 0ull;

    // x tile load addressing: 2 float4 per thread (256 tok x 8 k)
    const int xtok = tid >> 1;             // 0..127 (+128 via r)
    const int xkq  = tid & 1;              // which float4 of the 8-k row
    // w tile load addressing: 1 float2 per thread (8 k x 64 exp)
    const int wrow = tid >> 5;             // 0..7
    const int wc2  = tid & 31;             // float2 column

    float4 xv[2];
    float2 wv;

    // ---- preload tile 0 ----
#pragma unroll
    for (int r = 0; r < 2; r++)
        xv[r] = *reinterpret_cast<const float4*>(
            &x[(size_t)(tok0 + xtok + 128 * r) * D_DIM + kbeg + 4 * xkq]);
    wv = *reinterpret_cast<const float2*>(&w[(size_t)(kbeg + wrow) * E_EXP + 2 * wc2]);
    {
#pragma unroll
        for (int r = 0; r < 2; r++) {
            int tok = xtok + 128 * r;
            xs[0][4 * xkq + 0][tok] = xv[r].x;
            xs[0][4 * xkq + 1][tok] = xv[r].y;
            xs[0][4 * xkq + 2][tok] = xv[r].z;
            xs[0][4 * xkq + 3][tok] = xv[r].w;
        }
        wsd[0][wrow][4 * wc2 + 0] = wv.x; wsd[0][wrow][4 * wc2 + 1] = wv.x;
        wsd[0][wrow][4 * wc2 + 2] = wv.y; wsd[0][wrow][4 * wc2 + 3] = wv.y;
    }
    __syncthreads();

#pragma unroll 1
    for (int t = 0; t < ntile; t++) {
        const int cur = t & 1;
        const bool more = (t + 1) < ntile;

        // prefetch tile t+1 into registers
        if (more) {
            const int k0 = kbeg + (t + 1) * KC;
#pragma unroll
            for (int r = 0; r < 2; r++)
                xv[r] = *reinterpret_cast<const float4*>(
                    &x[(size_t)(tok0 + xtok + 128 * r) * D_DIM + k0 + 4 * xkq]);
            wv = *reinterpret_cast<const float2*>(&w[(size_t)(k0 + wrow) * E_EXP + 2 * wc2]);
        }

        // compute 8 k on current buffer
#pragma unroll
        for (int kk = 0; kk < KC; kk++) {
            // 8 dup-expert pairs for this warp (broadcast LDS.128 x4)
            ulonglong2 q0 = *reinterpret_cast<const ulonglong2*>(&wsd[cur][kk][16 * wid + 0]);
            ulonglong2 q1 = *reinterpret_cast<const ulonglong2*>(&wsd[cur][kk][16 * wid + 4]);
            ulonglong2 q2 = *reinterpret_cast<const ulonglong2*>(&wsd[cur][kk][16 * wid + 8]);
            ulonglong2 q3 = *reinterpret_cast<const ulonglong2*>(&wsd[cur][kk][16 * wid + 12]);
            unsigned long long w2[8] = {q0.x, q0.y, q1.x, q1.y, q2.x, q2.y, q3.x, q3.y};

            // 4 adjacent-token pairs: tokens 8*lane .. 8*lane+7 (2 LDS.128)
            ulonglong2 xa = *reinterpret_cast<const ulonglong2*>(&xs[cur][kk][8 * lane]);
            ulonglong2 xb = *reinterpret_cast<const ulonglong2*>(&xs[cur][kk][8 * lane + 4]);
            unsigned long long xp[4] = {xa.x, xa.y, xb.x, xb.y};

#pragma unroll
            for (int j = 0; j < 4; j++)
#pragma unroll
                for (int e = 0; e < 8; e++)
                    ffma2(acc[j][e], xp[j], w2[e]);
        }

        // stage tile t+1 into the other buffer
        if (more) {
            const int nxt = cur ^ 1;
#pragma unroll
            for (int r = 0; r < 2; r++) {
                int tok = xtok + 128 * r;
                xs[nxt][4 * xkq + 0][tok] = xv[r].x;
                xs[nxt][4 * xkq + 1][tok] = xv[r].y;
                xs[nxt][4 * xkq + 2][tok] = xv[r].z;
                xs[nxt][4 * xkq + 3][tok] = xv[r].w;
            }
            wsd[nxt][wrow][4 * wc2 + 0] = wv.x; wsd[nxt][wrow][4 * wc2 + 1] = wv.x;
            wsd[nxt][wrow][4 * wc2 + 2] = wv.y; wsd[nxt][wrow][4 * wc2 + 3] = wv.y;
        }
        __syncthreads();
    }

    // store panel partials: per expert, thread owns 8 consecutive tokens -> 2 STG.128
#pragma unroll
    for (int e = 0; e < 8; e++) {
        float v0, v1, v2, v3, v4, v5, v6, v7;
        unpack2(acc[0][e], v0, v1);
        unpack2(acc[1][e], v2, v3);
        unpack2(acc[2][e], v4, v5);
        unpack2(acc[3][e], v6, v7);
        float* dst = &g_part[p][blockIdx.x][8 * wid + e][8 * lane];
        *reinterpret_cast<float4*>(dst + 0) = make_float4(v0, v1, v2, v3);
        *reinterpret_cast<float4*>(dst + 4) = make_float4(v4, v5, v6, v7);
    }
}

// ---- fold + topk: 256 CTAs x 128 threads; 32 tokens per CTA ----
__global__ __launch_bounds__(128) void fold_topk_kernel(float* __restrict__ out)
{
    __shared__ float lgs[32][67];    // [token-in-cta][expert], pad 67 (stride 3 banks)

    const int tid = threadIdx.x;
    const int tb  = blockIdx.x >> 3;            // token block (g_part dim)
    const int t0  = (blockIdx.x & 7) * 32;      // token offset within block

    // fold: items = 8 token-quads x 64 experts; 4 iterations of 128 threads.
    // lane-major = token quad -> fully coalesced LDG.128.
#pragma unroll
    for (int it = 0; it < 4; it++) {
        const int idx = it * 128 + tid;
        const int tg  = idx & 7;               // token quad
        const int e   = idx >> 3;              // expert
        float s0 = 0.f, s1 = 0.f, s2 = 0.f, s3 = 0.f;
#pragma unroll
        for (int p = 0; p < NPAN; p++) {
            float4 v = *reinterpret_cast<const float4*>(&g_part[p][tb][e][t0 + 4 * tg]);
            s0 = fadd_rn(s0, v.x);
            s1 = fadd_rn(s1, v.y);
            s2 = fadd_rn(s2, v.z);
            s3 = fadd_rn(s3, v.w);
        }
        lgs[4 * tg + 0][e] = s0;
        lgs[4 * tg + 1][e] = s1;
        lgs[4 * tg + 2][e] = s2;
        lgs[4 * tg + 3][e] = s3;
    }
    __syncthreads();

    // topk + softmax: threads 0..31, one token each (scan with strict > on
    // ascending e => tie -> lower index; mask by index; same ops as before)
    if (tid < 32) {
        float lg[E_EXP];
#pragma unroll
        for (int e = 0; e < E_EXP; e++) lg[e] = lgs[tid][e];

        float topv[TOPK]; int topi[TOPK];
#pragma unroll
        for (int s = 0; s < TOPK; s++) {
            float best = -CUDART_INF_F; int bi = 0;
#pragma unroll
            for (int e = 0; e < E_EXP; e++)
                if (lg[e] > best) { best = lg[e]; bi = e; }
            topv[s] = best; topi[s] = bi;
#pragma unroll
            for (int e = 0; e < E_EXP; e++)
                lg[e] = (e == bi) ? -CUDART_INF_F : lg[e];
        }

        const float m = topv[0];
        float ev[TOPK]; float ssum = 0.f;
#pragma unroll
        for (int q = 0; q < TOPK; q++) { ev[q] = expf(topv[q] - m); ssum = fadd_rn(ssum, ev[q]); }

        const int gtok = tb * TBLK + t0 + tid;
        const size_t base = (size_t)gtok * TOPK;
#pragma unroll
        for (int q = 0; q < TOPK; q++) {
            out[base + q] = fdiv_rn(ev[q], ssum);
            out[(size_t)T_TOK * TOPK + base + q] = (float)topi[q];
        }
    }
}

extern "C" void kernel_launch(void* const* d_in, const int* in_sizes, int n_in,
                              void* d_out, int out_size) {
    const float* x = (const float*)d_in[0];   // [8192, 4096]
    const float* w = (const float*)d_in[1];   // [4096, 64]
    float* out = (float*)d_out;

    gemm_panel_kernel<<<dim3(NTB, NPAN), 256>>>(x, w);
    fold_topk_kernel<<<T_TOK / 32, 128>>>(out);
}